// round 14
// baseline (speedup 1.0000x reference)
#include <cuda_runtime.h>
#include <cuda_fp16.h>
#include <math.h>
#include <stdint.h>

// Problem constants
#define BQ   4
#define LQ   513
#define DM   768
#define DI   1536
#define DRk  48
#define BL   (BQ*LQ)          // 2052
#define BLDM (BL*DM)
#define BLDI (BL*DI)
#define XZSZ (BL*2*DI)
#define DBL80 (BL*80)
#define XPSZ (BQ*512*256)

// fp32 scratch
__device__ __align__(256) float g_h  [BLDM];
__device__ __align__(256) float g_res[BLDM];
__device__ __align__(256) float g_xn [BLDM];
__device__ __align__(256) float g_xz [XZSZ];
__device__ __align__(256) float g_c  [2*BLDI];
__device__ __align__(256) float g_dt [2*BLDI];
__device__ __align__(256) float g_dbl[2*DBL80];
__device__ __align__(256) float g_y  [BLDI];
__device__ __align__(256) float g_yb [BLDI];
__device__ __align__(256) float g_xp [XPSZ];

// fp16 2-term split operands.  A rows: [hi|lo];  B (weight) rows: [hi|hi]
#define WE_IN_SZ  ((size_t)24*3072*1536)
#define WE_OUT_SZ ((size_t)24*768*3072)
#define WE_X_SZ   ((size_t)24*160*3072)
#define WE_DT_SZ  ((size_t)24*3072*128)
#define AE_XN_SZ  ((size_t)2052*1536)
#define AE_C_SZ   ((size_t)4104*3072)
__device__ __align__(256) __half g_we_in [WE_IN_SZ];
__device__ __align__(256) __half g_we_out[WE_OUT_SZ];
__device__ __align__(256) __half g_we_x  [WE_X_SZ];
__device__ __align__(256) __half g_we_dt [WE_DT_SZ];
__device__ __align__(256) __half g_ae_xn [AE_XN_SZ];
__device__ __align__(256) __half g_ae_c  [AE_C_SZ];

// ---------------------------------------------------------------------------
__device__ __forceinline__ uint32_t smem_u32(const void* p){
    uint32_t a;
    asm("{ .reg .u64 t; cvta.to.shared.u64 t, %1; cvt.u32.u64 %0, t; }" : "=r"(a) : "l"(p));
    return a;
}
__device__ __forceinline__ void cp16(uint32_t dst, const void* src, bool valid){
    int sz = valid ? 16 : 0;
    asm volatile("cp.async.ca.shared.global [%0], [%1], 16, %2;"
                 :: "r"(dst), "l"(src), "r"(sz) : "memory");
}
#define CP_COMMIT() asm volatile("cp.async.commit_group;" ::: "memory")
#define LDM_X4(r, addr) \
    asm volatile("ldmatrix.sync.aligned.m8n8.x4.shared.b16 {%0,%1,%2,%3}, [%4];" \
        : "=r"((r)[0]), "=r"((r)[1]), "=r"((r)[2]), "=r"((r)[3]) : "r"(addr))
__device__ __forceinline__ void mma16816(float* d, const uint32_t* a, uint32_t b0, uint32_t b1){
    asm volatile(
      "mma.sync.aligned.m16n8k16.row.col.f32.f16.f16.f32 "
      "{%0,%1,%2,%3}, {%4,%5,%6,%7}, {%8,%9}, {%0,%1,%2,%3};"
      : "+f"(d[0]), "+f"(d[1]), "+f"(d[2]), "+f"(d[3])
      : "r"(a[0]), "r"(a[1]), "r"(a[2]), "r"(a[3]), "r"(b0), "r"(b1));
}
__device__ __forceinline__ void split_fp16(float x, __half& hi, __half& lo){
    hi = __float2half_rn(x);
    lo = __float2half_rn(x - __half2float(hi));
}

// ---------------------------------------------------------------------------
// Fused weight converter (one launch): B-side layout [hi|hi]
// ---------------------------------------------------------------------------
__global__ void cvt_w_all(const float* __restrict__ w_in, const float* __restrict__ w_out,
                          const float* __restrict__ w_x,  const float* __restrict__ w_dt)
{
    long idx = (long)blockIdx.x*256 + threadIdx.x;
    const long S0 = (long)24*3072*768;    // w_in  rows*Kpad
    const long S1 = (long)24*768*1536;    // w_out
    const long S2 = (long)3840*1536;      // w_x (24*2*80 rows)
    const long S3 = (long)73728*64;       // w_dt (24*2*1536 rows, Kpad 64)
    const float* src; __half* dst; int K, Kpad, stride; long rel;
    if      (idx < S0)          { src=w_in;  dst=g_we_in;  K=768;  Kpad=768;  stride=768;  rel=idx; }
    else if (idx < S0+S1)       { src=w_out; dst=g_we_out; K=1536; Kpad=1536; stride=1536; rel=idx-S0; }
    else if (idx < S0+S1+S2)    { src=w_x;   dst=g_we_x;   K=1536; Kpad=1536; stride=1536; rel=idx-S0-S1; }
    else if (idx < S0+S1+S2+S3) { src=w_dt;  dst=g_we_dt;  K=48;   Kpad=64;   stride=48;   rel=idx-S0-S1-S2; }
    else return;
    long r = rel / Kpad; int k = (int)(rel - r*Kpad);
    float x = (k < K) ? src[r*stride + k] : 0.f;
    __half hi = __float2half_rn(x);
    __half* row = dst + r*2*Kpad;
    row[k] = hi; row[Kpad+k] = hi;
}

// ---------------------------------------------------------------------------
// HMMA fp16 GEMM: C[m][n] = sum_k Aext[m][k]*Bext[n][k]
// 128x128 tile, 8 warps (each 64x32), BK=64, 3-stage cp.async pipeline.
// amode: 0 = A is fp16 ext [hi|lo] (cp.async)
//        1 = A is fp32, value = 0.5*(A[r]+A2[r]); split on the fly (STS)
//        2 = A is fp32 single array; split on the fly (STS)
// epi: 0 none, 1 softplus(+bias). ksplit>1 -> atomicAdd (no epi).
// ---------------------------------------------------------------------------
#define SROW 144               // bytes per smem row (64 fp16 + 16B pad)
#define OPBUF (128*SROW)       // 18432 per operand
#define STGSZ (2*OPBUF)        // 36864 per stage
#define NSTG  3
#define GEMM_SMEM (NSTG*STGSZ) // 110592

__global__ void __launch_bounds__(256,2) gemm_mma(
    const void* __restrict__ Aptr, int ldaE, size_t aStr,
    const float* __restrict__ A2,
    const __half* __restrict__ Bg, int ldbE, size_t bStr,
    float* __restrict__ Cg, int ldc, size_t cStr,
    int M, int N, int Kext, int Kvalid,
    const float* __restrict__ bias, int biasStr,
    int ksplit, int epi, int amode)
{
    extern __shared__ char smem[];
    const int tid  = threadIdx.x;
    const int lane = tid & 31;
    const int wid  = tid >> 5;
    uint32_t sbase = smem_u32(smem);

    const int bz    = blockIdx.z;
    const int batch = bz / ksplit;
    const int ks    = bz - batch*ksplit;
    const __half* Ah = (const __half*)Aptr + (size_t)batch*aStr;
    const float*  Af = (const float*)Aptr + (size_t)batch*aStr;
    const __half* B  = Bg + (size_t)batch*bStr;
    float* C = Cg + (size_t)batch*cStr;
    const int row0 = blockIdx.y*128;
    const int col0 = blockIdx.x*128;
    const int kTot = Kext / ksplit;
    const int kstart = ks * kTot;
    const int nch = kTot / 64;
    const int halfK = Kext >> 1;

    // stage loader: 128 rows x 64 fp16 per operand, 16B chunks
    const int lr = tid >> 3, lg = tid & 7;     // base row 0..31, group 0..7
    auto load_stage = [&](int ci, int slot){
        int kb = kstart + ci*64;
        uint32_t base = sbase + slot*STGSZ;
        if (amode == 0) {
            #pragma unroll
            for (int q = 0; q < 4; q++) {
                int r = lr + q*32;
                uint32_t d = base + (uint32_t)r*SROW + lg*16;
                bool av = (row0 + r) < M;
                cp16(d,         Ah + (size_t)(av ? row0 + r : 0)*ldaE + kb + lg*8, av);
                bool bv = (col0 + r) < N;
                cp16(d + OPBUF, B + (size_t)(bv ? col0 + r : 0)*ldbE + kb + lg*8, bv);
            }
        } else {
            bool isHi = kb < halfK;
            int cb = (isHi ? kb : kb - halfK) + lg*8;
            #pragma unroll
            for (int q = 0; q < 4; q++) {
                int r = lr + q*32;
                uint32_t d = base + (uint32_t)r*SROW + lg*16;
                __half tmp[8];
                if (row0 + r < M) {
                    const float* s1 = Af + (size_t)(row0+r)*ldaE;
                    #pragma unroll
                    for (int j = 0; j < 8; j++) {
                        int cc = cb + j;
                        float v = 0.f;
                        if (cc < Kvalid) {
                            v = s1[cc];
                            if (amode == 1)
                                v = 0.5f*(v + A2[(size_t)(row0+r)*ldaE + cc]);
                        }
                        __half hi = __float2half_rn(v);
                        tmp[j] = isHi ? hi : __float2half_rn(v - __half2float(hi));
                    }
                } else {
                    #pragma unroll
                    for (int j = 0; j < 8; j++) tmp[j] = __float2half_rn(0.f);
                }
                *(uint4*)(smem + (d - sbase)) = *(const uint4*)tmp;
                bool bv = (col0 + r) < N;
                cp16(d + OPBUF, B + (size_t)(bv ? col0 + r : 0)*ldbE + kb + lg*8, bv);
            }
        }
        CP_COMMIT();
    };

    float acc[4][4][4];
    #pragma unroll
    for (int i=0;i<4;i++) for (int j=0;j<4;j++) for (int q=0;q<4;q++) acc[i][j][q]=0.f;

    const int wm = (wid >> 2) * 64;
    const int wn = (wid & 3) * 32;
    const uint32_t aOff = (uint32_t)(wm + (lane & 15))*SROW + (uint32_t)((lane >> 4) << 3)*2;
    const uint32_t bOff = OPBUF + (uint32_t)(wn + (lane & 7) + ((lane >> 4) << 3))*SROW
                        + (uint32_t)(((lane >> 3) & 1) << 3)*2;

    // prologue: stages 0,1
    load_stage(0, 0);
    if (1 < nch) load_stage(1, 1); else CP_COMMIT();

    int cur = 0, pfs = 2;
    for (int ci = 0; ci < nch; ci++) {
        asm volatile("cp.async.wait_group 1;" ::: "memory");
        __syncthreads();
        int pf = ci + 2;
        if (pf < nch) load_stage(pf, pfs);
        else CP_COMMIT();

        uint32_t stg = sbase + cur*STGSZ;
        #pragma unroll
        for (int k16 = 0; k16 < 4; k16++) {
            uint32_t kOff = (uint32_t)(k16*16)*2;
            uint32_t afr[4][4];
            #pragma unroll
            for (int mi = 0; mi < 4; mi++)
                LDM_X4(afr[mi], stg + aOff + (uint32_t)(mi*16)*SROW + kOff);
            uint32_t bfr[2][4];
            #pragma unroll
            for (int nj = 0; nj < 2; nj++)
                LDM_X4(bfr[nj], stg + bOff + (uint32_t)(nj*16)*SROW + kOff);
            #pragma unroll
            for (int mi = 0; mi < 4; mi++)
                #pragma unroll
                for (int ni = 0; ni < 4; ni++)
                    mma16816(acc[mi][ni], afr[mi],
                             bfr[ni>>1][(ni&1)*2], bfr[ni>>1][(ni&1)*2+1]);
        }
        cur = (cur == NSTG-1) ? 0 : cur+1;
        pfs = (pfs == NSTG-1) ? 0 : pfs+1;
    }

    // epilogue (direct from regs)
    #pragma unroll
    for (int mi = 0; mi < 4; mi++) {
        #pragma unroll
        for (int ni = 0; ni < 4; ni++) {
            float* d = acc[mi][ni];
            int gc = col0 + wn + ni*8 + 2*(lane & 3);
            int gr = row0 + wm + mi*16 + (lane >> 2);
            #pragma unroll
            for (int hf = 0; hf < 2; hf++) {
                int r = gr + hf*8;
                float v0 = d[hf*2+0], v1 = d[hf*2+1];
                if (r < M) {
                    if (ksplit > 1) {
                        if (gc   < N) atomicAdd(&C[(size_t)r*ldc + gc],   v0);
                        if (gc+1 < N) atomicAdd(&C[(size_t)r*ldc + gc+1], v1);
                    } else {
                        if (bias) {
                            v0 += bias[(size_t)batch*biasStr + gc];
                            v1 += bias[(size_t)batch*biasStr + gc + 1];
                        }
                        if (epi == 1) {
                            v0 = (v0 > 15.f) ? v0 : log1pf(expf(v0));
                            v1 = (v1 > 15.f) ? v1 : log1pf(expf(v1));
                        }
                        *(float2*)&C[(size_t)r*ldc + gc] = make_float2(v0, v1);
                    }
                }
            }
        }
    }
}

// ---------------------------------------------------------------------------
// FFMA SGEMM (patch embed only)
// ---------------------------------------------------------------------------
template<int BM,int BN,int BK,int TM,int TN>
__global__ void __launch_bounds__(256) sgemm_nt(
    const float* __restrict__ A, int lda,
    const float* __restrict__ B, int ldb,
    float*       __restrict__ C, int ldc,
    int M, int N, int K, const float* __restrict__ bias)
{
    const int row0 = blockIdx.y * BM;
    const int col0 = blockIdx.x * BN;
    __shared__ float As[BK][BM+4];
    __shared__ float Bs[BK][BN+4];
    const int tid = threadIdx.x;
    const int NT  = BN / TN;
    const int tx  = tid % NT, ty = tid / NT;
    float acc[TM][TN];
    #pragma unroll
    for (int i=0;i<TM;i++) for (int j=0;j<TN;j++) acc[i][j]=0.f;
    const int KQ = BK/4, lr0 = tid/KQ, lk = (tid%KQ)*4, RS = 256/KQ;
    for (int kb=0; kb<K; kb+=BK) {
        #pragma unroll
        for (int r=lr0;r<BM;r+=RS){
            float4 v=make_float4(0,0,0,0);
            if (row0+r<M) v=*(const float4*)(A+(size_t)(row0+r)*lda+kb+lk);
            As[lk+0][r]=v.x;As[lk+1][r]=v.y;As[lk+2][r]=v.z;As[lk+3][r]=v.w;
        }
        #pragma unroll
        for (int r=lr0;r<BN;r+=RS){
            float4 v=make_float4(0,0,0,0);
            if (col0+r<N) v=*(const float4*)(B+(size_t)(col0+r)*ldb+kb+lk);
            Bs[lk+0][r]=v.x;Bs[lk+1][r]=v.y;Bs[lk+2][r]=v.z;Bs[lk+3][r]=v.w;
        }
        __syncthreads();
        #pragma unroll
        for (int kk=0;kk<BK;kk++){
            float af[TM], bf[TN];
            #pragma unroll
            for (int i=0;i<TM;i+=4) *(float4*)&af[i]=*(const float4*)&As[kk][ty*TM+i];
            #pragma unroll
            for (int j=0;j<TN;j+=4) *(float4*)&bf[j]=*(const float4*)&Bs[kk][tx*TN+j];
            #pragma unroll
            for (int i=0;i<TM;i++) for (int j=0;j<TN;j++) acc[i][j]+=af[i]*bf[j];
        }
        __syncthreads();
    }
    #pragma unroll
    for (int i=0;i<TM;i++){
        int r=row0+ty*TM+i; if(r>=M) continue;
        #pragma unroll
        for (int j=0;j<TN;j++){
            int c=col0+tx*TN+j; if(c>=N) continue;
            float v=acc[i][j];
            if (bias) v+=bias[c];
            C[(size_t)r*ldc+c]=v;
        }
    }
}

// ---------------------------------------------------------------------------
__global__ void patch_gather(const float* __restrict__ x)
{
    int idx = blockIdx.x*256 + threadIdx.x;
    if (idx >= XPSZ) return;
    int inner = idx & 255;
    int p     = (idx >> 8) & 511;
    int b     = idx >> 17;
    int f = p >> 6, t = p & 63;
    int i = inner >> 4, j = inner & 15;
    g_xp[idx] = x[(size_t)b*131072 + (size_t)(f*16+i)*1024 + (t*16+j)];
}

// cls+pos assemble, also zero-init res (replaces memset)
__global__ void assemble_tok(const float* __restrict__ cls,
                             const float* __restrict__ pos)
{
    int idx = blockIdx.x*256 + threadIdx.x;
    if (idx >= BLDM) return;
    int m = idx % DM;
    int l = (idx / DM) % LQ;
    int b = idx / (DM*LQ);
    float v = (l == 0) ? cls[m] : g_xn[((size_t)b*512 + (l-1))*DM + m];
    g_h[idx]   = v + pos[(size_t)l*DM + m];
    g_res[idx] = 0.f;
}

// res += h ; ae_xn = split(rmsnorm(res)*ln_w)  (one block per token row)
__global__ void resnorm_kernel(const float* __restrict__ lnw)
{
    int r = blockIdx.x;
    int tid = threadIdx.x;
    size_t base = (size_t)r * DM;
    float v[3];
    float ss = 0.f;
    #pragma unroll
    for (int q=0;q<3;q++) {
        int i = tid + q*256;
        float t = g_res[base+i] + g_h[base+i];
        g_res[base+i] = t;
        v[q] = t;
        ss += t*t;
    }
    #pragma unroll
    for (int o=16;o;o>>=1) ss += __shfl_xor_sync(0xffffffffu, ss, o);
    __shared__ float sred[8];
    __shared__ float sscale;
    if ((tid & 31) == 0) sred[tid>>5] = ss;
    __syncthreads();
    if (tid == 0) {
        float t = 0.f;
        #pragma unroll
        for (int w=0;w<8;w++) t += sred[w];
        sscale = rsqrtf(t/(float)DM + 1e-5f);
    }
    __syncthreads();
    float sc = sscale;
    __half* row = g_ae_xn + (size_t)r*1536;
    #pragma unroll
    for (int q=0;q<3;q++) {
        int i = tid + q*256;
        float val = v[q]*sc*lnw[i];
        __half hi, lo; split_fp16(val, hi, lo);
        row[i] = hi; row[768+i] = lo;
    }
}

// conv+SiLU; writes g_c (fp32, for scan) and ae_c (fp16 split, for w_x GEMM).
// Also zeroes g_dbl (consumed by the next kernel's split-K atomics).
__global__ void conv_silu(const float* __restrict__ cw,
                          const float* __restrict__ cb)
{
    size_t idx = (size_t)blockIdx.x*256 + threadIdx.x;
    if (idx < (size_t)2*DBL80) g_dbl[idx] = 0.f;
    if (idx >= (size_t)2*BLDI) return;
    int d  = (int)(idx % DI);
    size_t t1 = idx / DI;
    int l  = (int)(t1 % LQ);
    int t2 = (int)(t1 / LQ);
    int b  = t2 % BQ;
    int br = t2 / BQ;
    const float* w = cw + ((size_t)br*DI + d)*4;
    float s = cb[(size_t)br*DI + d];
    #pragma unroll
    for (int k=0;k<4;k++) {
        int j = l - 3 + k;
        if (j >= 0) {
            int pj = br ? (512 - j) : j;
            s += w[k] * g_xz[((size_t)b*LQ + pj)*(2*DI) + d];
        }
    }
    float cval = s / (1.f + __expf(-s));
    g_c[idx] = cval;
    __half hi, lo; split_fp16(cval, hi, lo);
    __half* row = g_ae_c + t1*3072;   // row index == (br*BQ+b)*LQ+l
    row[d] = hi; row[1536+d] = lo;
}

// Selective scan: forward branch -> g_y, backward -> g_yb (plain stores).
__global__ void __launch_bounds__(128) ssm_scan_kernel(
    const float* __restrict__ a_log, const float* __restrict__ dd, int lyr)
{
    const int br = blockIdx.z;
    const int b  = blockIdx.y;
    const int d  = blockIdx.x*128 + threadIdx.x;

    const float* __restrict__ cC   = g_c  + ((size_t)(br*BQ+b))*LQ*DI + d;
    const float* __restrict__ dtC  = g_dt + ((size_t)(br*BQ+b))*LQ*DI + d;
    const float* __restrict__ dblC = g_dbl + (size_t)br*DBL80 + (size_t)b*LQ*80;
    const float* __restrict__ zC   = g_xz + (size_t)b*LQ*(2*DI) + DI + d;
    float*       __restrict__ yC   = (br ? g_yb : g_y) + (size_t)b*LQ*DI + d;

    float A[16], h[16];
    size_t ab = (((size_t)lyr*2 + br)*DI + d)*16;
    #pragma unroll
    for (int s=0;s<16;s++) { A[s] = -__expf(a_log[ab+s]); h[s] = 0.f; }
    const float Dd = dd[((size_t)lyr*2 + br)*DI + d];

    float n_dt = dtC[0];
    float n_u  = cC[0];
    float n_z  = zC[(size_t)(br ? 512 : 0)*(2*DI)];
    float4 nB[4], nC[4];
    {
        const float4* rb = (const float4*)(dblC + 48);
        #pragma unroll
        for (int q=0;q<4;q++) { nB[q] = rb[q]; nC[q] = rb[4+q]; }
    }

    for (int l = 0; l < LQ; l++) {
        float dtv = n_dt, uv = n_u, zv = n_z;
        float Bb[16], Cc[16];
        #pragma unroll
        for (int q=0;q<4;q++) { *(float4*)&Bb[4*q] = nB[q]; *(float4*)&Cc[4*q] = nC[q]; }

        if (l + 1 < LQ) {
            size_t off = (size_t)(l+1)*DI;
            n_dt = dtC[off];
            n_u  = cC[off];
            int zl = br ? (512-(l+1)) : (l+1);
            n_z  = zC[(size_t)zl*(2*DI)];
            const float4* rb = (const float4*)(dblC + (size_t)(l+1)*80 + 48);
            #pragma unroll
            for (int q=0;q<4;q++) { nB[q] = rb[q]; nC[q] = rb[4+q]; }
        }

        float du = dtv*uv;
        float yv = 0.f;
        #pragma unroll
        for (int s=0;s<16;s++) {
            h[s] = __expf(dtv*A[s])*h[s] + du*Bb[s];
            yv  += h[s]*Cc[s];
        }
        float sg   = zv / (1.f + __expf(-zv));
        float outv = (yv + uv*Dd) * sg;
        int ol = br ? (512 - l) : l;
        yC[(size_t)ol*DI] = outv;
    }
}

__global__ void final_ln(const float* __restrict__ fw,
                         const float* __restrict__ fb,
                         float* __restrict__ out)
{
    int b = blockIdx.x;
    int tid = threadIdx.x;
    size_t base = (size_t)b*LQ*DM;
    float v[3];
    float s = 0.f;
    #pragma unroll
    for (int q=0;q<3;q++) {
        int i = tid + q*256;
        float t = g_res[base+i] + g_h[base+i];
        v[q] = t;
        s += t;
    }
    __shared__ float sred[8];
    __shared__ float sval;
    #pragma unroll
    for (int o=16;o;o>>=1) s += __shfl_xor_sync(0xffffffffu, s, o);
    if ((tid&31)==0) sred[tid>>5] = s;
    __syncthreads();
    if (tid==0) { float t=0.f; for(int w=0;w<8;w++) t+=sred[w]; sval = t/(float)DM; }
    __syncthreads();
    float mean = sval;
    float vv = 0.f;
    #pragma unroll
    for (int q=0;q<3;q++) { float dv = v[q]-mean; vv += dv*dv; }
    #pragma unroll
    for (int o=16;o;o>>=1) vv += __shfl_xor_sync(0xffffffffu, vv, o);
    __syncthreads();
    if ((tid&31)==0) sred[tid>>5] = vv;
    __syncthreads();
    if (tid==0) { float t=0.f; for(int w=0;w<8;w++) t+=sred[w]; sval = rsqrtf(t/(float)DM + 1e-5f); }
    __syncthreads();
    float inv = sval;
    #pragma unroll
    for (int q=0;q<3;q++) {
        int i = tid + q*256;
        out[(size_t)b*DM + i] = (v[q]-mean)*inv*fw[i] + fb[i];
    }
}

// ---------------------------------------------------------------------------
static inline unsigned cdiv(size_t a, unsigned b){ return (unsigned)((a + b - 1) / b); }

extern "C" void kernel_launch(void* const* d_in, const int* in_sizes, int n_in,
                              void* d_out, int out_size)
{
    (void)in_sizes; (void)n_in; (void)out_size;
    const float* x       = (const float*)d_in[0];
    const float* patch_w = (const float*)d_in[1];
    const float* patch_b = (const float*)d_in[2];
    const float* cls     = (const float*)d_in[3];
    const float* pos     = (const float*)d_in[4];
    const float* ln_w    = (const float*)d_in[5];
    const float* w_in    = (const float*)d_in[6];
    const float* conv_w  = (const float*)d_in[7];
    const float* conv_b  = (const float*)d_in[8];
    const float* w_x     = (const float*)d_in[9];
    const float* w_dt    = (const float*)d_in[10];
    const float* b_dt    = (const float*)d_in[11];
    const float* a_log   = (const float*)d_in[12];
    const float* dd      = (const float*)d_in[13];
    const float* w_out   = (const float*)d_in[14];
    const float* fn_w    = (const float*)d_in[15];
    const float* fn_b    = (const float*)d_in[16];
    float* out = (float*)d_out;

    float *p_res, *p_xn, *p_xz, *p_c, *p_dt, *p_dbl, *p_xp, *p_h, *p_y, *p_yb;
    cudaGetSymbolAddress((void**)&p_h,   g_h);
    cudaGetSymbolAddress((void**)&p_res, g_res);
    cudaGetSymbolAddress((void**)&p_xn,  g_xn);
    cudaGetSymbolAddress((void**)&p_xz,  g_xz);
    cudaGetSymbolAddress((void**)&p_c,   g_c);
    cudaGetSymbolAddress((void**)&p_dt,  g_dt);
    cudaGetSymbolAddress((void**)&p_dbl, g_dbl);
    cudaGetSymbolAddress((void**)&p_xp,  g_xp);
    cudaGetSymbolAddress((void**)&p_y,   g_y);
    cudaGetSymbolAddress((void**)&p_yb,  g_yb);
    __half *we_in, *we_out, *we_x, *we_dt, *ae_xn, *ae_c;
    cudaGetSymbolAddress((void**)&we_in,  g_we_in);
    cudaGetSymbolAddress((void**)&we_out, g_we_out);
    cudaGetSymbolAddress((void**)&we_x,   g_we_x);
    cudaGetSymbolAddress((void**)&we_dt,  g_we_dt);
    cudaGetSymbolAddress((void**)&ae_xn,  g_ae_xn);
    cudaGetSymbolAddress((void**)&ae_c,   g_ae_c);

    cudaFuncSetAttribute(gemm_mma, cudaFuncAttributeMaxDynamicSharedMemorySize, GEMM_SMEM);

    // ---- weights: one fused convert launch ----
    {
        size_t total = (size_t)24*3072*768 + (size_t)24*768*1536
                     + (size_t)3840*1536 + (size_t)73728*64;
        cvt_w_all<<<cdiv(total,256),256>>>(w_in, w_out, w_x, w_dt);
    }

    // ---- patch embed ----
    patch_gather<<<XPSZ/256, 256>>>(x);
    sgemm_nt<128,128,8,8,8><<<dim3(6,16,1),256>>>(p_xp,256, patch_w,256,
                                                  p_xn,DM, 2048, DM, 256, patch_b);
    assemble_tok<<<BLDM/256, 256>>>(cls, pos);

    for (int lyr = 0; lyr < 24; lyr++) {
        resnorm_kernel<<<BL,256>>>(ln_w + (size_t)lyr*DM);

        // xz = xn @ w_in^T  (2052 x 3072, Kext=1536)
        gemm_mma<<<dim3(24,17,1),256,GEMM_SMEM>>>(
            ae_xn, 1536, 0, nullptr,
            we_in + (size_t)lyr*3072*1536, 1536, 0,
            p_xz, 3072, 0,
            BL, 3072, 1536, 1536, nullptr, 0, 1, 0, 0);

        conv_silu<<<cdiv((size_t)2*BLDI,256),256>>>(
            conv_w + (size_t)lyr*2*DI*4, conv_b + (size_t)lyr*2*DI);

        // dbl = c @ w_x^T  (2 batches, 2052 x 80, Kext=3072, split-K=4)
        gemm_mma<<<dim3(1,17,8),256,GEMM_SMEM>>>(
            ae_c, 3072, (size_t)2052*3072, nullptr,
            we_x + (size_t)lyr*160*3072, 3072, (size_t)80*3072,
            p_dbl, 80, (size_t)DBL80,
            BL, 80, 3072, 3072, nullptr, 0, 4, 0, 0);

        // dt = softplus(dbl[:, :48] @ w_dt^T + b_dt)  (2 batches, Kext=128,
        // A read as fp32 stride 80, Kvalid 48, split on the fly)
        gemm_mma<<<dim3(12,17,2),256,GEMM_SMEM>>>(
            p_dbl, 80, (size_t)DBL80, nullptr,
            we_dt + (size_t)lyr*3072*128, 128, (size_t)1536*128,
            p_dt, DI, (size_t)BLDI,
            BL, DI, 128, 48,
            b_dt + (size_t)lyr*2*DI, DI, 1, 1, 2);

        ssm_scan_kernel<<<dim3(12,4,2),128>>>(a_log, dd, lyr);

        // h = (0.5*(y+yb)) @ w_out^T  (2052 x 768, Kext=3072, fp32-avg A mode)
        gemm_mma<<<dim3(6,17,1),256,GEMM_SMEM>>>(
            p_y, DI, 0, p_yb,
            we_out + (size_t)lyr*768*3072, 3072, 0,
            p_h, DM, 0,
            BL, DM, 3072, 1536, nullptr, 0, 1, 0, 1);
    }

    final_ln<<<4,256>>>(fn_w, fn_b, out);
}

// round 16
// speedup vs baseline: 1.3176x; 1.3176x over previous
#include <cuda_runtime.h>
#include <cuda_fp16.h>
#include <math.h>
#include <stdint.h>

// Problem constants
#define BQ   4
#define LQ   513
#define DM   768
#define DI   1536
#define DRk  48
#define BL   (BQ*LQ)          // 2052
#define BLDM (BL*DM)
#define BLDI (BL*DI)
#define XZSZ (BL*2*DI)
#define DBL80 (BL*80)
#define XPSZ (BQ*512*256)

// fp32 scratch
__device__ __align__(256) float g_h  [BLDM];
__device__ __align__(256) float g_res[BLDM];
__device__ __align__(256) float g_xn [BLDM];
__device__ __align__(256) float g_xz [XZSZ];
__device__ __align__(256) float g_c  [2*BLDI];
__device__ __align__(256) float g_dt [2*BLDI];
__device__ __align__(256) float g_dbl[2*DBL80];
__device__ __align__(256) float g_y  [BLDI];
__device__ __align__(256) float g_yb [BLDI];
__device__ __align__(256) float g_xp [XPSZ];

// fp16 2-term split operands.  A rows: [hi|lo];  B (weight) rows: [hi|hi]
#define WE_IN_SZ  ((size_t)24*3072*1536)
#define WE_OUT_SZ ((size_t)24*768*3072)
#define WE_X_SZ   ((size_t)24*160*3072)
#define WE_DT_SZ  ((size_t)24*3072*128)
#define AE_XN_SZ  ((size_t)2052*1536)
#define AE_C_SZ   ((size_t)4104*3072)
#define AE_DT_SZ  ((size_t)4104*128)
#define AE_Y_SZ   ((size_t)2052*3072)
__device__ __align__(256) __half g_we_in [WE_IN_SZ];
__device__ __align__(256) __half g_we_out[WE_OUT_SZ];
__device__ __align__(256) __half g_we_x  [WE_X_SZ];
__device__ __align__(256) __half g_we_dt [WE_DT_SZ];
__device__ __align__(256) __half g_ae_xn [AE_XN_SZ];
__device__ __align__(256) __half g_ae_c  [AE_C_SZ];
__device__ __align__(256) __half g_ae_dt [AE_DT_SZ];
__device__ __align__(256) __half g_ae_y  [AE_Y_SZ];

// ---------------------------------------------------------------------------
__device__ __forceinline__ uint32_t smem_u32(const void* p){
    uint32_t a;
    asm("{ .reg .u64 t; cvta.to.shared.u64 t, %1; cvt.u32.u64 %0, t; }" : "=r"(a) : "l"(p));
    return a;
}
__device__ __forceinline__ void cp16(uint32_t dst, const void* src, bool valid){
    int sz = valid ? 16 : 0;
    asm volatile("cp.async.ca.shared.global [%0], [%1], 16, %2;"
                 :: "r"(dst), "l"(src), "r"(sz) : "memory");
}
#define CP_COMMIT() asm volatile("cp.async.commit_group;" ::: "memory")
#define LDM_X4(r, addr) \
    asm volatile("ldmatrix.sync.aligned.m8n8.x4.shared.b16 {%0,%1,%2,%3}, [%4];" \
        : "=r"((r)[0]), "=r"((r)[1]), "=r"((r)[2]), "=r"((r)[3]) : "r"(addr))
__device__ __forceinline__ void mma16816(float* d, const uint32_t* a, uint32_t b0, uint32_t b1){
    asm volatile(
      "mma.sync.aligned.m16n8k16.row.col.f32.f16.f16.f32 "
      "{%0,%1,%2,%3}, {%4,%5,%6,%7}, {%8,%9}, {%0,%1,%2,%3};"
      : "+f"(d[0]), "+f"(d[1]), "+f"(d[2]), "+f"(d[3])
      : "r"(a[0]), "r"(a[1]), "r"(a[2]), "r"(a[3]), "r"(b0), "r"(b1));
}
__device__ __forceinline__ void split_fp16(float x, __half& hi, __half& lo){
    hi = __float2half_rn(x);
    lo = __float2half_rn(x - __half2float(hi));
}

// ---------------------------------------------------------------------------
// Fused weight converter (one launch): B-side layout [hi|hi]
// ---------------------------------------------------------------------------
__global__ void cvt_w_all(const float* __restrict__ w_in, const float* __restrict__ w_out,
                          const float* __restrict__ w_x,  const float* __restrict__ w_dt)
{
    long idx = (long)blockIdx.x*256 + threadIdx.x;
    const long S0 = (long)24*3072*768;    // w_in  rows*Kpad
    const long S1 = (long)24*768*1536;    // w_out
    const long S2 = (long)3840*1536;      // w_x (24*2*80 rows)
    const long S3 = (long)73728*64;       // w_dt (24*2*1536 rows, Kpad 64)
    const float* src; __half* dst; int K, Kpad, stride; long rel;
    if      (idx < S0)          { src=w_in;  dst=g_we_in;  K=768;  Kpad=768;  stride=768;  rel=idx; }
    else if (idx < S0+S1)       { src=w_out; dst=g_we_out; K=1536; Kpad=1536; stride=1536; rel=idx-S0; }
    else if (idx < S0+S1+S2)    { src=w_x;   dst=g_we_x;   K=1536; Kpad=1536; stride=1536; rel=idx-S0-S1; }
    else if (idx < S0+S1+S2+S3) { src=w_dt;  dst=g_we_dt;  K=48;   Kpad=64;   stride=48;   rel=idx-S0-S1-S2; }
    else return;
    long r = rel / Kpad; int k = (int)(rel - r*Kpad);
    float x = (k < K) ? src[r*stride + k] : 0.f;
    __half hi = __float2half_rn(x);
    __half* row = dst + r*2*Kpad;
    row[k] = hi; row[Kpad+k] = hi;
}

// A-side converter (dbl -> ae_dt): [hi|lo]
__global__ void cvt_a(const float* __restrict__ src, __half* __restrict__ dst,
                      int rows, int K, int Kpad, int srcStride)
{
    int idx = blockIdx.x*256 + threadIdx.x;
    if (idx >= rows*Kpad) return;
    int r = idx / Kpad, k = idx - r*Kpad;
    float x = (k < K) ? src[(size_t)r*srcStride + k] : 0.f;
    __half hi, lo; split_fp16(x, hi, lo);
    __half* row = dst + (size_t)r*2*Kpad;
    row[k] = hi; row[Kpad+k] = lo;
}

// ---------------------------------------------------------------------------
// HMMA fp16 GEMM (R12-proven): 128x128 tile, 8 warps, BK=64, 3-stage cp.async.
// epi: 0 none, 1 softplus(+bias). ksplit>1 -> atomicAdd (no epi).
// ---------------------------------------------------------------------------
#define SROW 144               // bytes per smem row (64 fp16 + 16B pad)
#define OPBUF (128*SROW)       // 18432 per operand
#define STGSZ (2*OPBUF)        // 36864 per stage
#define NSTG  3
#define GEMM_SMEM (NSTG*STGSZ) // 110592

__global__ void __launch_bounds__(256,2) gemm_mma(
    const __half* __restrict__ Ag, int ldaE, size_t aStr,
    const __half* __restrict__ Bg, int ldbE, size_t bStr,
    float* __restrict__ Cg, int ldc, size_t cStr,
    int M, int N, int Kext,
    const float* __restrict__ bias, int biasStr,
    int ksplit, int epi)
{
    extern __shared__ char smem[];
    const int tid  = threadIdx.x;
    const int lane = tid & 31;
    const int wid  = tid >> 5;
    uint32_t sbase = smem_u32(smem);

    const int bz    = blockIdx.z;
    const int batch = bz / ksplit;
    const int ks    = bz - batch*ksplit;
    const __half* A = Ag + (size_t)batch*aStr;
    const __half* B = Bg + (size_t)batch*bStr;
    float* C = Cg + (size_t)batch*cStr;
    const int row0 = blockIdx.y*128;
    const int col0 = blockIdx.x*128;
    const int kTot = Kext / ksplit;
    const int kstart = ks * kTot;
    const int nch = kTot / 64;

    // stage loader: 128 rows x 64 fp16 per operand, 16B chunks
    const int lr = tid >> 3, lg = tid & 7;     // base row 0..31, group 0..7
    auto load_stage = [&](int ci, int slot){
        int kb = kstart + ci*64;
        uint32_t base = sbase + slot*STGSZ;
        #pragma unroll
        for (int q = 0; q < 4; q++) {
            int r = lr + q*32;
            uint32_t d = base + (uint32_t)r*SROW + lg*16;
            bool av = (row0 + r) < M;
            cp16(d,         A + (size_t)(av ? row0 + r : 0)*ldaE + kb + lg*8, av);
            bool bv = (col0 + r) < N;
            cp16(d + OPBUF, B + (size_t)(bv ? col0 + r : 0)*ldbE + kb + lg*8, bv);
        }
        CP_COMMIT();
    };

    float acc[4][4][4];
    #pragma unroll
    for (int i=0;i<4;i++) for (int j=0;j<4;j++) for (int q=0;q<4;q++) acc[i][j][q]=0.f;

    const int wm = (wid >> 2) * 64;
    const int wn = (wid & 3) * 32;
    const uint32_t aOff = (uint32_t)(wm + (lane & 15))*SROW + (uint32_t)((lane >> 4) << 3)*2;
    const uint32_t bOff = OPBUF + (uint32_t)(wn + (lane & 7) + ((lane >> 4) << 3))*SROW
                        + (uint32_t)(((lane >> 3) & 1) << 3)*2;

    // prologue: stages 0,1
    load_stage(0, 0);
    if (1 < nch) load_stage(1, 1); else CP_COMMIT();

    int cur = 0, pfs = 2;
    for (int ci = 0; ci < nch; ci++) {
        asm volatile("cp.async.wait_group 1;" ::: "memory");
        __syncthreads();
        int pf = ci + 2;
        if (pf < nch) load_stage(pf, pfs);
        else CP_COMMIT();

        uint32_t stg = sbase + cur*STGSZ;
        #pragma unroll
        for (int k16 = 0; k16 < 4; k16++) {
            uint32_t kOff = (uint32_t)(k16*16)*2;
            uint32_t afr[4][4];
            #pragma unroll
            for (int mi = 0; mi < 4; mi++)
                LDM_X4(afr[mi], stg + aOff + (uint32_t)(mi*16)*SROW + kOff);
            uint32_t bfr[2][4];
            #pragma unroll
            for (int nj = 0; nj < 2; nj++)
                LDM_X4(bfr[nj], stg + bOff + (uint32_t)(nj*16)*SROW + kOff);
            #pragma unroll
            for (int mi = 0; mi < 4; mi++)
                #pragma unroll
                for (int ni = 0; ni < 4; ni++)
                    mma16816(acc[mi][ni], afr[mi],
                             bfr[ni>>1][(ni&1)*2], bfr[ni>>1][(ni&1)*2+1]);
        }
        cur = (cur == NSTG-1) ? 0 : cur+1;
        pfs = (pfs == NSTG-1) ? 0 : pfs+1;
    }

    // epilogue (direct from regs)
    #pragma unroll
    for (int mi = 0; mi < 4; mi++) {
        #pragma unroll
        for (int ni = 0; ni < 4; ni++) {
            float* d = acc[mi][ni];
            int gc = col0 + wn + ni*8 + 2*(lane & 3);
            int gr = row0 + wm + mi*16 + (lane >> 2);
            #pragma unroll
            for (int hf = 0; hf < 2; hf++) {
                int r = gr + hf*8;
                float v0 = d[hf*2+0], v1 = d[hf*2+1];
                if (r < M) {
                    if (ksplit > 1) {
                        if (gc   < N) atomicAdd(&C[(size_t)r*ldc + gc],   v0);
                        if (gc+1 < N) atomicAdd(&C[(size_t)r*ldc + gc+1], v1);
                    } else {
                        if (bias) {
                            v0 += bias[(size_t)batch*biasStr + gc];
                            v1 += bias[(size_t)batch*biasStr + gc + 1];
                        }
                        if (epi == 1) {
                            v0 = (v0 > 15.f) ? v0 : log1pf(expf(v0));
                            v1 = (v1 > 15.f) ? v1 : log1pf(expf(v1));
                        }
                        *(float2*)&C[(size_t)r*ldc + gc] = make_float2(v0, v1);
                    }
                }
            }
        }
    }
}

// ---------------------------------------------------------------------------
// FFMA SGEMM (patch embed only)
// ---------------------------------------------------------------------------
template<int BM,int BN,int BK,int TM,int TN>
__global__ void __launch_bounds__(256) sgemm_nt(
    const float* __restrict__ A, int lda,
    const float* __restrict__ B, int ldb,
    float*       __restrict__ C, int ldc,
    int M, int N, int K, const float* __restrict__ bias)
{
    const int row0 = blockIdx.y * BM;
    const int col0 = blockIdx.x * BN;
    __shared__ float As[BK][BM+4];
    __shared__ float Bs[BK][BN+4];
    const int tid = threadIdx.x;
    const int NT  = BN / TN;
    const int tx  = tid % NT, ty = tid / NT;
    float acc[TM][TN];
    #pragma unroll
    for (int i=0;i<TM;i++) for (int j=0;j<TN;j++) acc[i][j]=0.f;
    const int KQ = BK/4, lr0 = tid/KQ, lk = (tid%KQ)*4, RS = 256/KQ;
    for (int kb=0; kb<K; kb+=BK) {
        #pragma unroll
        for (int r=lr0;r<BM;r+=RS){
            float4 v=make_float4(0,0,0,0);
            if (row0+r<M) v=*(const float4*)(A+(size_t)(row0+r)*lda+kb+lk);
            As[lk+0][r]=v.x;As[lk+1][r]=v.y;As[lk+2][r]=v.z;As[lk+3][r]=v.w;
        }
        #pragma unroll
        for (int r=lr0;r<BN;r+=RS){
            float4 v=make_float4(0,0,0,0);
            if (col0+r<N) v=*(const float4*)(B+(size_t)(col0+r)*ldb+kb+lk);
            Bs[lk+0][r]=v.x;Bs[lk+1][r]=v.y;Bs[lk+2][r]=v.z;Bs[lk+3][r]=v.w;
        }
        __syncthreads();
        #pragma unroll
        for (int kk=0;kk<BK;kk++){
            float af[TM], bf[TN];
            #pragma unroll
            for (int i=0;i<TM;i+=4) *(float4*)&af[i]=*(const float4*)&As[kk][ty*TM+i];
            #pragma unroll
            for (int j=0;j<TN;j+=4) *(float4*)&bf[j]=*(const float4*)&Bs[kk][tx*TN+j];
            #pragma unroll
            for (int i=0;i<TM;i++) for (int j=0;j<TN;j++) acc[i][j]+=af[i]*bf[j];
        }
        __syncthreads();
    }
    #pragma unroll
    for (int i=0;i<TM;i++){
        int r=row0+ty*TM+i; if(r>=M) continue;
        #pragma unroll
        for (int j=0;j<TN;j++){
            int c=col0+tx*TN+j; if(c>=N) continue;
            float v=acc[i][j];
            if (bias) v+=bias[c];
            C[(size_t)r*ldc+c]=v;
        }
    }
}

// ---------------------------------------------------------------------------
__global__ void patch_gather(const float* __restrict__ x)
{
    int idx = blockIdx.x*256 + threadIdx.x;
    if (idx >= XPSZ) return;
    int inner = idx & 255;
    int p     = (idx >> 8) & 511;
    int b     = idx >> 17;
    int f = p >> 6, t = p & 63;
    int i = inner >> 4, j = inner & 15;
    g_xp[idx] = x[(size_t)b*131072 + (size_t)(f*16+i)*1024 + (t*16+j)];
}

// cls+pos assemble, also zero-init res (replaces memset)
__global__ void assemble_tok(const float* __restrict__ cls,
                             const float* __restrict__ pos)
{
    int idx = blockIdx.x*256 + threadIdx.x;
    if (idx >= BLDM) return;
    int m = idx % DM;
    int l = (idx / DM) % LQ;
    int b = idx / (DM*LQ);
    float v = (l == 0) ? cls[m] : g_xn[((size_t)b*512 + (l-1))*DM + m];
    g_h[idx]   = v + pos[(size_t)l*DM + m];
    g_res[idx] = 0.f;
}

// res += h ; ae_xn = split(rmsnorm(res)*ln_w)  (one block per token row)
__global__ void resnorm_kernel(const float* __restrict__ lnw)
{
    int r = blockIdx.x;
    int tid = threadIdx.x;
    size_t base = (size_t)r * DM;
    float v[3];
    float ss = 0.f;
    #pragma unroll
    for (int q=0;q<3;q++) {
        int i = tid + q*256;
        float t = g_res[base+i] + g_h[base+i];
        g_res[base+i] = t;
        v[q] = t;
        ss += t*t;
    }
    #pragma unroll
    for (int o=16;o;o>>=1) ss += __shfl_xor_sync(0xffffffffu, ss, o);
    __shared__ float sred[8];
    __shared__ float sscale;
    if ((tid & 31) == 0) sred[tid>>5] = ss;
    __syncthreads();
    if (tid == 0) {
        float t = 0.f;
        #pragma unroll
        for (int w=0;w<8;w++) t += sred[w];
        sscale = rsqrtf(t/(float)DM + 1e-5f);
    }
    __syncthreads();
    float sc = sscale;
    __half* row = g_ae_xn + (size_t)r*1536;
    #pragma unroll
    for (int q=0;q<3;q++) {
        int i = tid + q*256;
        float val = v[q]*sc*lnw[i];
        __half hi, lo; split_fp16(val, hi, lo);
        row[i] = hi; row[768+i] = lo;
    }
}

// conv+SiLU; writes g_c (fp32, for scan) and ae_c (fp16 split, for w_x GEMM).
// Also zeroes g_dbl (consumed two kernels later by split-K atomics).
__global__ void conv_silu(const float* __restrict__ cw,
                          const float* __restrict__ cb)
{
    size_t idx = (size_t)blockIdx.x*256 + threadIdx.x;
    if (idx < (size_t)2*DBL80) g_dbl[idx] = 0.f;
    if (idx >= (size_t)2*BLDI) return;
    int d  = (int)(idx % DI);
    size_t t1 = idx / DI;
    int l  = (int)(t1 % LQ);
    int t2 = (int)(t1 / LQ);
    int b  = t2 % BQ;
    int br = t2 / BQ;
    const float* w = cw + ((size_t)br*DI + d)*4;
    float s = cb[(size_t)br*DI + d];
    #pragma unroll
    for (int k=0;k<4;k++) {
        int j = l - 3 + k;
        if (j >= 0) {
            int pj = br ? (512 - j) : j;
            s += w[k] * g_xz[((size_t)b*LQ + pj)*(2*DI) + d];
        }
    }
    float cval = s / (1.f + __expf(-s));
    g_c[idx] = cval;
    __half hi, lo; split_fp16(cval, hi, lo);
    __half* row = g_ae_c + t1*3072;   // row index == (br*BQ+b)*LQ+l
    row[d] = hi; row[1536+d] = lo;
}

// Selective scan: forward branch -> g_y, backward -> g_yb (plain stores).
__global__ void __launch_bounds__(128) ssm_scan_kernel(
    const float* __restrict__ a_log, const float* __restrict__ dd, int lyr)
{
    const int br = blockIdx.z;
    const int b  = blockIdx.y;
    const int d  = blockIdx.x*128 + threadIdx.x;

    const float* __restrict__ cC   = g_c  + ((size_t)(br*BQ+b))*LQ*DI + d;
    const float* __restrict__ dtC  = g_dt + ((size_t)(br*BQ+b))*LQ*DI + d;
    const float* __restrict__ dblC = g_dbl + (size_t)br*DBL80 + (size_t)b*LQ*80;
    const float* __restrict__ zC   = g_xz + (size_t)b*LQ*(2*DI) + DI + d;
    float*       __restrict__ yC   = (br ? g_yb : g_y) + (size_t)b*LQ*DI + d;

    float A[16], h[16];
    size_t ab = (((size_t)lyr*2 + br)*DI + d)*16;
    #pragma unroll
    for (int s=0;s<16;s++) { A[s] = -__expf(a_log[ab+s]); h[s] = 0.f; }
    const float Dd = dd[((size_t)lyr*2 + br)*DI + d];

    float n_dt = dtC[0];
    float n_u  = cC[0];
    float n_z  = zC[(size_t)(br ? 512 : 0)*(2*DI)];
    float4 nB[4], nC[4];
    {
        const float4* rb = (const float4*)(dblC + 48);
        #pragma unroll
        for (int q=0;q<4;q++) { nB[q] = rb[q]; nC[q] = rb[4+q]; }
    }

    for (int l = 0; l < LQ; l++) {
        float dtv = n_dt, uv = n_u, zv = n_z;
        float Bb[16], Cc[16];
        #pragma unroll
        for (int q=0;q<4;q++) { *(float4*)&Bb[4*q] = nB[q]; *(float4*)&Cc[4*q] = nC[q]; }

        if (l + 1 < LQ) {
            size_t off = (size_t)(l+1)*DI;
            n_dt = dtC[off];
            n_u  = cC[off];
            int zl = br ? (512-(l+1)) : (l+1);
            n_z  = zC[(size_t)zl*(2*DI)];
            const float4* rb = (const float4*)(dblC + (size_t)(l+1)*80 + 48);
            #pragma unroll
            for (int q=0;q<4;q++) { nB[q] = rb[q]; nC[q] = rb[4+q]; }
        }

        float du = dtv*uv;
        float yv = 0.f;
        #pragma unroll
        for (int s=0;s<16;s++) {
            h[s] = __expf(dtv*A[s])*h[s] + du*Bb[s];
            yv  += h[s]*Cc[s];
        }
        float sg   = zv / (1.f + __expf(-zv));
        float outv = (yv + uv*Dd) * sg;
        int ol = br ? (512 - l) : l;
        yC[(size_t)ol*DI] = outv;
    }
}

// combine branches + fp16 split for w_out GEMM (vectorized: 4 elems/thread)
__global__ void y_combine(void)
{
    int idx4 = blockIdx.x*256 + threadIdx.x;
    if (idx4 >= BLDI/4) return;
    int idx = idx4*4;
    int r = idx / DI, d = idx - r*DI;
    float4 a = *(const float4*)&g_y [idx];
    float4 b = *(const float4*)&g_yb[idx];
    float v[4] = {0.5f*(a.x+b.x), 0.5f*(a.y+b.y), 0.5f*(a.z+b.z), 0.5f*(a.w+b.w)};
    __half hi[4], lo[4];
    #pragma unroll
    for (int j=0;j<4;j++) split_fp16(v[j], hi[j], lo[j]);
    __half* row = g_ae_y + (size_t)r*3072;
    *(uint2*)&row[d]       = *(const uint2*)hi;
    *(uint2*)&row[1536+d]  = *(const uint2*)lo;
}

__global__ void final_ln(const float* __restrict__ fw,
                         const float* __restrict__ fb,
                         float* __restrict__ out)
{
    int b = blockIdx.x;
    int tid = threadIdx.x;
    size_t base = (size_t)b*LQ*DM;
    float v[3];
    float s = 0.f;
    #pragma unroll
    for (int q=0;q<3;q++) {
        int i = tid + q*256;
        float t = g_res[base+i] + g_h[base+i];
        v[q] = t;
        s += t;
    }
    __shared__ float sred[8];
    __shared__ float sval;
    #pragma unroll
    for (int o=16;o;o>>=1) s += __shfl_xor_sync(0xffffffffu, s, o);
    if ((tid&31)==0) sred[tid>>5] = s;
    __syncthreads();
    if (tid==0) { float t=0.f; for(int w=0;w<8;w++) t+=sred[w]; sval = t/(float)DM; }
    __syncthreads();
    float mean = sval;
    float vv = 0.f;
    #pragma unroll
    for (int q=0;q<3;q++) { float dv = v[q]-mean; vv += dv*dv; }
    #pragma unroll
    for (int o=16;o;o>>=1) vv += __shfl_xor_sync(0xffffffffu, vv, o);
    __syncthreads();
    if ((tid&31)==0) sred[tid>>5] = vv;
    __syncthreads();
    if (tid==0) { float t=0.f; for(int w=0;w<8;w++) t+=sred[w]; sval = rsqrtf(t/(float)DM + 1e-5f); }
    __syncthreads();
    float inv = sval;
    #pragma unroll
    for (int q=0;q<3;q++) {
        int i = tid + q*256;
        out[(size_t)b*DM + i] = (v[q]-mean)*inv*fw[i] + fb[i];
    }
}

// ---------------------------------------------------------------------------
static inline unsigned cdiv(size_t a, unsigned b){ return (unsigned)((a + b - 1) / b); }

extern "C" void kernel_launch(void* const* d_in, const int* in_sizes, int n_in,
                              void* d_out, int out_size)
{
    (void)in_sizes; (void)n_in; (void)out_size;
    const float* x       = (const float*)d_in[0];
    const float* patch_w = (const float*)d_in[1];
    const float* patch_b = (const float*)d_in[2];
    const float* cls     = (const float*)d_in[3];
    const float* pos     = (const float*)d_in[4];
    const float* ln_w    = (const float*)d_in[5];
    const float* w_in    = (const float*)d_in[6];
    const float* conv_w  = (const float*)d_in[7];
    const float* conv_b  = (const float*)d_in[8];
    const float* w_x     = (const float*)d_in[9];
    const float* w_dt    = (const float*)d_in[10];
    const float* b_dt    = (const float*)d_in[11];
    const float* a_log   = (const float*)d_in[12];
    const float* dd      = (const float*)d_in[13];
    const float* w_out   = (const float*)d_in[14];
    const float* fn_w    = (const float*)d_in[15];
    const float* fn_b    = (const float*)d_in[16];
    float* out = (float*)d_out;

    float *p_res, *p_xn, *p_xz, *p_c, *p_dt, *p_dbl, *p_xp, *p_h;
    cudaGetSymbolAddress((void**)&p_h,   g_h);
    cudaGetSymbolAddress((void**)&p_res, g_res);
    cudaGetSymbolAddress((void**)&p_xn,  g_xn);
    cudaGetSymbolAddress((void**)&p_xz,  g_xz);
    cudaGetSymbolAddress((void**)&p_c,   g_c);
    cudaGetSymbolAddress((void**)&p_dt,  g_dt);
    cudaGetSymbolAddress((void**)&p_dbl, g_dbl);
    cudaGetSymbolAddress((void**)&p_xp,  g_xp);
    __half *we_in, *we_out, *we_x, *we_dt, *ae_xn, *ae_c, *ae_dt, *ae_y;
    cudaGetSymbolAddress((void**)&we_in,  g_we_in);
    cudaGetSymbolAddress((void**)&we_out, g_we_out);
    cudaGetSymbolAddress((void**)&we_x,   g_we_x);
    cudaGetSymbolAddress((void**)&we_dt,  g_we_dt);
    cudaGetSymbolAddress((void**)&ae_xn,  g_ae_xn);
    cudaGetSymbolAddress((void**)&ae_c,   g_ae_c);
    cudaGetSymbolAddress((void**)&ae_dt,  g_ae_dt);
    cudaGetSymbolAddress((void**)&ae_y,   g_ae_y);

    cudaFuncSetAttribute(gemm_mma, cudaFuncAttributeMaxDynamicSharedMemorySize, GEMM_SMEM);

    // ---- weights: one fused convert launch ----
    {
        size_t total = (size_t)24*3072*768 + (size_t)24*768*1536
                     + (size_t)3840*1536 + (size_t)73728*64;
        cvt_w_all<<<cdiv(total,256),256>>>(w_in, w_out, w_x, w_dt);
    }

    // ---- patch embed ----
    patch_gather<<<XPSZ/256, 256>>>(x);
    sgemm_nt<128,128,8,8,8><<<dim3(6,16,1),256>>>(p_xp,256, patch_w,256,
                                                  p_xn,DM, 2048, DM, 256, patch_b);
    assemble_tok<<<BLDM/256, 256>>>(cls, pos);

    for (int lyr = 0; lyr < 24; lyr++) {
        resnorm_kernel<<<BL,256>>>(ln_w + (size_t)lyr*DM);

        // xz = xn @ w_in^T  (2052 x 3072, Kext=1536)
        gemm_mma<<<dim3(24,17,1),256,GEMM_SMEM>>>(
            ae_xn, 1536, 0,
            we_in + (size_t)lyr*3072*1536, 1536, 0,
            p_xz, 3072, 0,
            BL, 3072, 1536, nullptr, 0, 1, 0);

        conv_silu<<<cdiv((size_t)2*BLDI,256),256>>>(
            conv_w + (size_t)lyr*2*DI*4, conv_b + (size_t)lyr*2*DI);

        // dbl = c @ w_x^T  (2 batches, 2052 x 80, Kext=3072, split-K=4)
        gemm_mma<<<dim3(1,17,8),256,GEMM_SMEM>>>(
            ae_c, 3072, (size_t)2052*3072,
            we_x + (size_t)lyr*160*3072, 3072, (size_t)80*3072,
            p_dbl, 80, (size_t)DBL80,
            BL, 80, 3072, nullptr, 0, 4, 0);

        // dt = softplus(dbl[:, :48] @ w_dt^T + b_dt)  (2 batches, Kext=128)
        cvt_a<<<cdiv((size_t)4104*64,256),256>>>(p_dbl, ae_dt, 4104, 48, 64, 80);
        gemm_mma<<<dim3(12,17,2),256,GEMM_SMEM>>>(
            ae_dt, 128, (size_t)2052*128,
            we_dt + (size_t)lyr*3072*128, 128, (size_t)1536*128,
            p_dt, DI, (size_t)BLDI,
            BL, DI, 128,
            b_dt + (size_t)lyr*2*DI, DI, 1, 1);

        ssm_scan_kernel<<<dim3(12,4,2),128>>>(a_log, dd, lyr);
        y_combine<<<cdiv(BLDI/4,256),256>>>();

        // h = y @ w_out^T  (2052 x 768, Kext=3072)
        gemm_mma<<<dim3(6,17,1),256,GEMM_SMEM>>>(
            ae_y, 3072, 0,
            we_out + (size_t)lyr*768*3072, 3072, 0,
            p_h, DM, 0,
            BL, DM, 3072, nullptr, 0, 1, 0);
    }

    final_ln<<<4,256>>>(fn_w, fn_b, out);
}